// round 1
// baseline (speedup 1.0000x reference)
#include <cuda_runtime.h>
#include <cstdint>

#define N 4096
#define D 128
#define BHALF 2048
#define INV_T 14.285714285714285714f  /* 1/0.07 */

// ---------------- scratch (static device globals; no allocation) ----------------
__device__ __align__(16) float    g_f[N * D];      // L2-normalized features, fp32
__device__ __align__(16) unsigned g_ftf[N * D];    // tf32-rounded copies (bit pattern)
__device__ int    g_cnt[N];
__device__ int    g_sidx[N * 64];
__device__ float  g_sval[N * 64];
__device__ float  g_partial[32 * N];               // per (j-tile, row) partial Z
__device__ float  g_lp[N];

// ---------------- K1: L2 normalize + tf32 copy ----------------
__global__ void k_norm(const float* __restrict__ feat) {
    int i = blockIdx.x, d = threadIdx.x;
    float v = feat[(size_t)i * D + d];
    float s = v * v;
    #pragma unroll
    for (int o = 16; o; o >>= 1) s += __shfl_xor_sync(0xffffffffu, s, o);
    __shared__ float ws[4];
    if ((d & 31) == 0) ws[d >> 5] = s;
    __syncthreads();
    float tot = ws[0] + ws[1] + ws[2] + ws[3];
    float f = v / sqrtf(tot);
    g_f[(size_t)i * D + d] = f;
    unsigned t;
    asm("cvt.rna.tf32.f32 %0, %1;" : "=r"(t) : "f"(f));
    g_ftf[(size_t)i * D + d] = t;
}

// ---------------- K2: row-wise sparsemax (Michelot fixed point) ----------------
__global__ void __launch_bounds__(512) k_sparsemax(const float* __restrict__ attn,
                                                   float* __restrict__ outm) {
    const int i = blockIdx.x;
    const int tid = threadIdx.x;
    __shared__ float z[N];
    __shared__ double sS[16];
    __shared__ int sC[16];
    __shared__ float s_tau;
    __shared__ int warpCnt[16];
    __shared__ int s_total;

    const float* row = attn + (size_t)i * N;
    for (int j = tid; j < N; j += 512) z[j] = row[j] * INV_T;
    __syncthreads();
    if (tid == 0) { z[i & (BHALF - 1)] = 0.f; z[(i & (BHALF - 1)) + BHALF] = 0.f; }
    __syncthreads();

    float tau = -3.402823466e38f;
    for (int it = 0; it < N; ++it) {
        double s = 0.0; int c = 0;
        for (int j = tid; j < N; j += 512) {
            float v = z[j];
            if (v > tau) { s += (double)v; c++; }
        }
        #pragma unroll
        for (int o = 16; o; o >>= 1) {
            s += __shfl_xor_sync(0xffffffffu, s, o);
            c += __shfl_xor_sync(0xffffffffu, c, o);
        }
        if ((tid & 31) == 0) { sS[tid >> 5] = s; sC[tid >> 5] = c; }
        __syncthreads();
        if (tid == 0) {
            double S = 0.0; int C = 0;
            for (int w = 0; w < 16; w++) { S += sS[w]; C += sC[w]; }
            s_tau = (float)((S - 1.0) / (double)C);
        }
        __syncthreads();
        float tn = s_tau;
        if (tn == tau) break;
        tau = tn;
        __syncthreads();
    }

    // write masked row + deterministic support compaction
    if (tid == 0) s_total = 0;
    __syncthreads();
    for (int base = 0; base < N; base += 512) {
        int j = base + tid;
        float m = z[j] - tau;
        m = fmaxf(m, 0.0f);
        outm[(size_t)i * N + j] = m;
        bool p = (m > 0.0f);
        unsigned bal = __ballot_sync(0xffffffffu, p);
        if ((tid & 31) == 0) warpCnt[tid >> 5] = __popc(bal);
        __syncthreads();
        if (tid == 0) {
            int run = s_total;
            for (int w = 0; w < 16; w++) { int t = warpCnt[w]; warpCnt[w] = run; run += t; }
            s_total = run;
        }
        __syncthreads();
        if (p) {
            int pos = warpCnt[tid >> 5] + __popc(bal & ((1u << (tid & 31)) - 1u));
            if (pos < 64) { g_sidx[i * 64 + pos] = j; g_sval[i * 64 + pos] = m; }
        }
        __syncthreads();
    }
    if (tid == 0) g_cnt[i] = s_total;
}

// ---------------- K3: fused tf32 Gram + exp + row partial sums ----------------
__device__ __forceinline__ void mma_tf32(float c[4], const unsigned a[4], const unsigned b[2]) {
    asm volatile(
        "mma.sync.aligned.m16n8k8.row.col.f32.tf32.tf32.f32 "
        "{%0,%1,%2,%3}, {%4,%5,%6,%7}, {%8,%9}, {%0,%1,%2,%3};\n"
        : "+f"(c[0]), "+f"(c[1]), "+f"(c[2]), "+f"(c[3])
        : "r"(a[0]), "r"(a[1]), "r"(a[2]), "r"(a[3]), "r"(b[0]), "r"(b[1]));
}

#define LDA 36

__global__ void __launch_bounds__(256) k_gemm() {
    const int bi = blockIdx.y, bj = blockIdx.x;
    __shared__ __align__(16) unsigned As[128 * LDA];
    __shared__ __align__(16) unsigned Bs[128 * LDA];
    __shared__ float sZ[128];

    const int tid = threadIdx.x;
    const int lane = tid & 31, wid = tid >> 5;
    const int wm = wid >> 1, wn = wid & 1;    // 4 x 2 warp grid -> warp tile 32x64
    const int g = lane >> 2, t4 = lane & 3;

    if (tid < 128) sZ[tid] = 0.0f;

    float acc[2][8][4];
    #pragma unroll
    for (int mt = 0; mt < 2; mt++)
        #pragma unroll
        for (int nt = 0; nt < 8; nt++)
            #pragma unroll
            for (int k = 0; k < 4; k++) acc[mt][nt][k] = 0.0f;

    const int lr = tid >> 1;              // load row 0..127
    const int lh = tid & 1;               // half selector

    for (int kc = 0; kc < 4; kc++) {
        // stage A and B k-chunks (128 x 32) into shared
        #pragma unroll
        for (int q = 0; q < 4; q++) {
            int cv = lh * 4 + q;          // column vector 0..7 (of uint4)
            uint4 va = *(const uint4*)(g_ftf + ((size_t)(bi * 128 + lr) * D + kc * 32 + cv * 4));
            *(uint4*)(As + lr * LDA + cv * 4) = va;
            uint4 vb = *(const uint4*)(g_ftf + ((size_t)(bj * 128 + lr) * D + kc * 32 + cv * 4));
            *(uint4*)(Bs + lr * LDA + cv * 4) = vb;
        }
        __syncthreads();

        #pragma unroll
        for (int ks = 0; ks < 4; ks++) {
            unsigned a[2][4], b[8][2];
            #pragma unroll
            for (int mt = 0; mt < 2; mt++) {
                int r0 = wm * 32 + mt * 16 + g;
                a[mt][0] = As[r0 * LDA + ks * 8 + t4];
                a[mt][1] = As[(r0 + 8) * LDA + ks * 8 + t4];
                a[mt][2] = As[r0 * LDA + ks * 8 + t4 + 4];
                a[mt][3] = As[(r0 + 8) * LDA + ks * 8 + t4 + 4];
            }
            #pragma unroll
            for (int nt = 0; nt < 8; nt++) {
                int c0 = wn * 64 + nt * 8 + g;
                b[nt][0] = Bs[c0 * LDA + ks * 8 + t4];
                b[nt][1] = Bs[c0 * LDA + ks * 8 + t4 + 4];
            }
            #pragma unroll
            for (int mt = 0; mt < 2; mt++)
                #pragma unroll
                for (int nt = 0; nt < 8; nt++) mma_tf32(acc[mt][nt], a[mt], b[nt]);
        }
        __syncthreads();
    }

    // epilogue: exp((dot-1)/T), exclude diagonal, reduce rows
    const int ibase = bi * 128, jbase = bj * 128;
    #pragma unroll
    for (int mt = 0; mt < 2; mt++) {
        int r0 = wm * 32 + mt * 16 + g;
        int gi0 = ibase + r0, gi1 = gi0 + 8;
        float rs0 = 0.f, rs1 = 0.f;
        #pragma unroll
        for (int nt = 0; nt < 8; nt++) {
            int c0 = wn * 64 + nt * 8 + t4 * 2;
            int gj0 = jbase + c0, gj1 = gj0 + 1;
            float e;
            e = __expf((acc[mt][nt][0] - 1.0f) * INV_T); if (gj0 == gi0) e = 0.f; rs0 += e;
            e = __expf((acc[mt][nt][1] - 1.0f) * INV_T); if (gj1 == gi0) e = 0.f; rs0 += e;
            e = __expf((acc[mt][nt][2] - 1.0f) * INV_T); if (gj0 == gi1) e = 0.f; rs1 += e;
            e = __expf((acc[mt][nt][3] - 1.0f) * INV_T); if (gj1 == gi1) e = 0.f; rs1 += e;
        }
        rs0 += __shfl_xor_sync(0xffffffffu, rs0, 1);
        rs0 += __shfl_xor_sync(0xffffffffu, rs0, 2);
        rs1 += __shfl_xor_sync(0xffffffffu, rs1, 1);
        rs1 += __shfl_xor_sync(0xffffffffu, rs1, 2);
        if (t4 == 0) {   // two warps (wn=0,1) add per row: commutative -> deterministic
            atomicAdd(&sZ[r0], rs0);
            atomicAdd(&sZ[r0 + 8], rs1);
        }
    }
    __syncthreads();
    if (tid < 128) g_partial[(size_t)bj * N + ibase + tid] = sZ[tid];
}

// ---------------- K4: per-row corrections + log-prob of positive ----------------
__global__ void k_rowfix(const float* __restrict__ outm) {
    const int i = blockIdx.x;
    const int d = threadIdx.x;
    const int lane = d & 31, w = d >> 5;
    __shared__ float fi[D];
    __shared__ float red[4];
    fi[d] = g_f[(size_t)i * D + d];
    __syncthreads();

    auto dotw = [&](int j) -> float {
        float p = fi[d] * g_f[(size_t)j * D + d];
        #pragma unroll
        for (int o = 16; o; o >>= 1) p += __shfl_xor_sync(0xffffffffu, p, o);
        if (lane == 0) red[w] = p;
        __syncthreads();
        float r = red[0] + red[1] + red[2] + red[3];
        __syncthreads();
        return r;
    };

    float simpos = (dotw(i ^ BHALF) - 1.0f) * INV_T;

    int cnt = g_cnt[i];
    float corr = 0.0f;
    if (cnt <= 64) {
        for (int k = 0; k < cnt; k++) {
            int j = g_sidx[i * 64 + k];
            float m = g_sval[i * 64 + k];
            corr += m * __expf((dotw(j) - 1.0f) * INV_T);
        }
    } else {
        for (int j = 0; j < N; j++) {
            float m = outm[(size_t)i * N + j];     // uniform broadcast load
            if (m > 0.0f) corr += m * __expf((dotw(j) - 1.0f) * INV_T);
        }
    }

    if (d == 0) {
        float Zs = 0.0f;
        for (int b = 0; b < 32; b++) Zs += g_partial[(size_t)b * N + i];
        float Z = Zs - corr;
        g_lp[i] = simpos - logf(Z);
    }
}

// ---------------- K5: loss reduction ----------------
__global__ void k_loss(float* __restrict__ out, int moff) {
    __shared__ float sm[512];
    int t = threadIdx.x;
    float s = 0.0f;
    #pragma unroll
    for (int k = 0; k < 8; k++) s += g_lp[t + k * 512];
    sm[t] = s;
    __syncthreads();
    for (int o = 256; o; o >>= 1) {
        if (t < o) sm[t] += sm[t + o];
        __syncthreads();
    }
    if (t == 0) {
        float loss = -(sm[0] / 4096.0f);
        for (int q = 0; q < moff; q++) out[q] = loss;
    }
}

// ---------------- launch ----------------
extern "C" void kernel_launch(void* const* d_in, const int* in_sizes, int n_in,
                              void* d_out, int out_size) {
    int fidx = (in_sizes[0] == N * D) ? 0 : 1;
    const float* feat = (const float*)d_in[fidx];
    const float* attn = (const float*)d_in[1 - fidx];
    float* out = (float*)d_out;

    long long nn = (long long)N * (long long)N;
    int moff = (int)((long long)out_size - nn);
    if (moff < 0) moff = 0;
    float* outm = out + moff;

    k_norm<<<N, D>>>(feat);
    k_sparsemax<<<N, 512>>>(attn, outm);
    k_gemm<<<dim3(32, 32), 256>>>();
    k_rowfix<<<N, D>>>(outm);
    k_loss<<<1, 512>>>(out, moff);
}

// round 3
// speedup vs baseline: 11.3124x; 11.3124x over previous
#include <cuda_runtime.h>
#include <cstdint>

#define N 4096
#define D 128
#define BHALF 2048
#define INV_T 14.285714285714285714f  /* 1/0.07 */

// ---------------- scratch (static device globals; no allocation) ----------------
__device__ __align__(16) float    g_f[N * D];      // L2-normalized features, fp32
__device__ __align__(16) unsigned g_ftf[N * D];    // tf32-rounded copies (bit pattern)
__device__ int    g_cnt[N];
__device__ int    g_sidx[N * 64];
__device__ float  g_sval[N * 64];
__device__ float  g_partial[32 * N];               // per (j-tile, row) partial Z
__device__ float  g_lp[N];

// ---------------- K1: L2 normalize + tf32 copy ----------------
__global__ void k_norm(const float* __restrict__ feat) {
    int i = blockIdx.x, d = threadIdx.x;
    float v = feat[(size_t)i * D + d];
    float s = v * v;
    #pragma unroll
    for (int o = 16; o; o >>= 1) s += __shfl_xor_sync(0xffffffffu, s, o);
    __shared__ float ws[4];
    if ((d & 31) == 0) ws[d >> 5] = s;
    __syncthreads();
    float tot = ws[0] + ws[1] + ws[2] + ws[3];
    float f = v / sqrtf(tot);
    g_f[(size_t)i * D + d] = f;
    unsigned t;
    asm("cvt.rna.tf32.f32 %0, %1;" : "=r"(t) : "f"(f));
    g_ftf[(size_t)i * D + d] = t;
}

// ---------------- K2: row-wise sparsemax via candidate pruning ----------------
// Support set of sparsemax satisfies z_j > tau >= z_max - 1, so only elements
// within 1.0 of the row max can be in the support. Gather those (typically 1-3),
// sort them, and evaluate the reference's sorted-cumsum formula exactly in fp32.
#define CAND_MAX 128

__global__ void __launch_bounds__(512) k_sparsemax(const float* __restrict__ attn,
                                                   float* __restrict__ outm) {
    const int i = blockIdx.x;
    const int tid = threadIdx.x;
    __shared__ float z[N];
    __shared__ float wred[16];
    __shared__ int   wcnt[16];
    __shared__ float s_max, s_tau;
    __shared__ int   s_ccnt, s_fb;
    __shared__ int   s_cidx[CAND_MAX];
    __shared__ float s_cval[CAND_MAX];

    const int j1 = i & (BHALF - 1);
    const int j2 = j1 + BHALF;
    const float4* row4 = (const float4*)(attn + (size_t)i * N);

    // pass A: load, scale, apply negative mask (zero the two positives/diag), track max
    float mx = -3.402823466e38f;
    #pragma unroll
    for (int it = 0; it < 2; it++) {
        int v = tid + it * 512;
        float4 r = row4[v];
        int j = v * 4;
        float z0 = (j     == j1 || j     == j2) ? 0.f : r.x * INV_T;
        float z1 = (j + 1 == j1 || j + 1 == j2) ? 0.f : r.y * INV_T;
        float z2 = (j + 2 == j1 || j + 2 == j2) ? 0.f : r.z * INV_T;
        float z3 = (j + 3 == j1 || j + 3 == j2) ? 0.f : r.w * INV_T;
        z[j] = z0; z[j + 1] = z1; z[j + 2] = z2; z[j + 3] = z3;
        mx = fmaxf(mx, fmaxf(fmaxf(z0, z1), fmaxf(z2, z3)));
    }
    #pragma unroll
    for (int o = 16; o; o >>= 1) mx = fmaxf(mx, __shfl_xor_sync(0xffffffffu, mx, o));
    if ((tid & 31) == 0) wred[tid >> 5] = mx;
    if (tid == 0) s_ccnt = 0;
    __syncthreads();
    if (tid == 0) {
        float m = wred[0];
        for (int w = 1; w < 16; w++) m = fmaxf(m, wred[w]);
        s_max = m;
    }
    __syncthreads();

    // pass B: gather candidates z >= max - 1
    const float thr = s_max - 1.0f;
    #pragma unroll
    for (int it = 0; it < 2; it++) {
        int j = (tid + it * 512) * 4;
        #pragma unroll
        for (int q = 0; q < 4; q++) {
            float v = z[j + q];
            if (v >= thr) {
                int p = atomicAdd(&s_ccnt, 1);
                if (p < CAND_MAX) { s_cidx[p] = j + q; s_cval[p] = v; }
            }
        }
    }
    __syncthreads();

    if (tid == 0) {
        int cnt = s_ccnt;
        s_fb = (cnt > CAND_MAX);
        if (!s_fb) {
            // insertion sort desc by (value, then index asc) -> deterministic
            for (int a = 1; a < cnt; a++) {
                float v = s_cval[a]; int ix = s_cidx[a];
                int b = a - 1;
                while (b >= 0 && (s_cval[b] < v || (s_cval[b] == v && s_cidx[b] > ix))) {
                    s_cval[b + 1] = s_cval[b]; s_cidx[b + 1] = s_cidx[b]; b--;
                }
                s_cval[b + 1] = v; s_cidx[b + 1] = ix;
            }
            // reference formula: fp32 sequential cumsum over descending values
            float cum = 0.f, cumkz = 1.f; int kz = 1;
            for (int k = 1; k <= cnt; k++) {
                float v = s_cval[k - 1];
                cum += v;
                if (1.0f + (float)k * v > cum) { kz = k; cumkz = cum; }
            }
            float tau = (cumkz - 1.0f) / (float)kz;
            s_tau = tau;
            g_cnt[i] = kz;
            int lim = kz < 64 ? kz : 64;
            for (int k = 0; k < lim; k++) {
                g_sidx[i * 64 + k] = s_cidx[k];
                g_sval[i * 64 + k] = s_cval[k] - tau;
            }
        }
    }
    __syncthreads();

    if (s_fb) {
        // fp32 Michelot fallback (never expected with this data, safety only)
        float tau = -3.402823466e38f;
        for (int iter = 0; iter < 64; iter++) {
            float s = 0.f; int c = 0;
            for (int j = tid; j < N; j += 512) {
                float v = z[j];
                if (v > tau) { s += v; c++; }
            }
            #pragma unroll
            for (int o = 16; o; o >>= 1) {
                s += __shfl_xor_sync(0xffffffffu, s, o);
                c += __shfl_xor_sync(0xffffffffu, c, o);
            }
            if ((tid & 31) == 0) { wred[tid >> 5] = s; wcnt[tid >> 5] = c; }
            __syncthreads();
            if (tid == 0) {
                float S = 0.f; int C = 0;
                for (int w = 0; w < 16; w++) { S += wred[w]; C += wcnt[w]; }
                s_tau = (S - 1.0f) / (float)C;
            }
            __syncthreads();
            float tn = s_tau;
            if (tn == tau) break;
            tau = tn;
            __syncthreads();
        }
        if (tid == 0) g_cnt[i] = N;   // force rowfix full-scan path
        __syncthreads();
    }

    // pass C: write masked row (scalar stores — outm may be only 4B-aligned)
    const float tau = s_tau;
    float* orow = outm + (size_t)i * N;
    #pragma unroll
    for (int it = 0; it < 8; it++) {
        int j = tid + it * 512;
        orow[j] = fmaxf(z[j] - tau, 0.f);
    }
}

// ---------------- K3: fused tf32 Gram + exp + row partial sums ----------------
__device__ __forceinline__ void mma_tf32(float c[4], const unsigned a[4], const unsigned b[2]) {
    asm volatile(
        "mma.sync.aligned.m16n8k8.row.col.f32.tf32.tf32.f32 "
        "{%0,%1,%2,%3}, {%4,%5,%6,%7}, {%8,%9}, {%0,%1,%2,%3};\n"
        : "+f"(c[0]), "+f"(c[1]), "+f"(c[2]), "+f"(c[3])
        : "r"(a[0]), "r"(a[1]), "r"(a[2]), "r"(a[3]), "r"(b[0]), "r"(b[1]));
}

#define LDA 36

__global__ void __launch_bounds__(256) k_gemm() {
    const int bi = blockIdx.y, bj = blockIdx.x;
    __shared__ __align__(16) unsigned As[128 * LDA];
    __shared__ __align__(16) unsigned Bs[128 * LDA];
    __shared__ float sZ[128];

    const int tid = threadIdx.x;
    const int lane = tid & 31, wid = tid >> 5;
    const int wm = wid >> 1, wn = wid & 1;    // 4 x 2 warp grid -> warp tile 32x64
    const int g = lane >> 2, t4 = lane & 3;

    if (tid < 128) sZ[tid] = 0.0f;

    float acc[2][8][4];
    #pragma unroll
    for (int mt = 0; mt < 2; mt++)
        #pragma unroll
        for (int nt = 0; nt < 8; nt++)
            #pragma unroll
            for (int k = 0; k < 4; k++) acc[mt][nt][k] = 0.0f;

    const int lr = tid >> 1;              // load row 0..127
    const int lh = tid & 1;               // half selector

    for (int kc = 0; kc < 4; kc++) {
        #pragma unroll
        for (int q = 0; q < 4; q++) {
            int cv = lh * 4 + q;          // column vector 0..7 (of uint4)
            uint4 va = *(const uint4*)(g_ftf + ((size_t)(bi * 128 + lr) * D + kc * 32 + cv * 4));
            *(uint4*)(As + lr * LDA + cv * 4) = va;
            uint4 vb = *(const uint4*)(g_ftf + ((size_t)(bj * 128 + lr) * D + kc * 32 + cv * 4));
            *(uint4*)(Bs + lr * LDA + cv * 4) = vb;
        }
        __syncthreads();

        #pragma unroll
        for (int ks = 0; ks < 4; ks++) {
            unsigned a[2][4], b[8][2];
            #pragma unroll
            for (int mt = 0; mt < 2; mt++) {
                int r0 = wm * 32 + mt * 16 + g;
                a[mt][0] = As[r0 * LDA + ks * 8 + t4];
                a[mt][1] = As[(r0 + 8) * LDA + ks * 8 + t4];
                a[mt][2] = As[r0 * LDA + ks * 8 + t4 + 4];
                a[mt][3] = As[(r0 + 8) * LDA + ks * 8 + t4 + 4];
            }
            #pragma unroll
            for (int nt = 0; nt < 8; nt++) {
                int c0 = wn * 64 + nt * 8 + g;
                b[nt][0] = Bs[c0 * LDA + ks * 8 + t4];
                b[nt][1] = Bs[c0 * LDA + ks * 8 + t4 + 4];
            }
            #pragma unroll
            for (int mt = 0; mt < 2; mt++)
                #pragma unroll
                for (int nt = 0; nt < 8; nt++) mma_tf32(acc[mt][nt], a[mt], b[nt]);
        }
        __syncthreads();
    }

    // epilogue: exp((dot-1)/T), exclude diagonal, reduce rows
    const int ibase = bi * 128, jbase = bj * 128;
    #pragma unroll
    for (int mt = 0; mt < 2; mt++) {
        int r0 = wm * 32 + mt * 16 + g;
        int gi0 = ibase + r0, gi1 = gi0 + 8;
        float rs0 = 0.f, rs1 = 0.f;
        #pragma unroll
        for (int nt = 0; nt < 8; nt++) {
            int c0 = wn * 64 + nt * 8 + t4 * 2;
            int gj0 = jbase + c0, gj1 = gj0 + 1;
            float e;
            e = __expf((acc[mt][nt][0] - 1.0f) * INV_T); if (gj0 == gi0) e = 0.f; rs0 += e;
            e = __expf((acc[mt][nt][1] - 1.0f) * INV_T); if (gj1 == gi0) e = 0.f; rs0 += e;
            e = __expf((acc[mt][nt][2] - 1.0f) * INV_T); if (gj0 == gi1) e = 0.f; rs1 += e;
            e = __expf((acc[mt][nt][3] - 1.0f) * INV_T); if (gj1 == gi1) e = 0.f; rs1 += e;
        }
        rs0 += __shfl_xor_sync(0xffffffffu, rs0, 1);
        rs0 += __shfl_xor_sync(0xffffffffu, rs0, 2);
        rs1 += __shfl_xor_sync(0xffffffffu, rs1, 1);
        rs1 += __shfl_xor_sync(0xffffffffu, rs1, 2);
        if (t4 == 0) {
            atomicAdd(&sZ[r0], rs0);
            atomicAdd(&sZ[r0 + 8], rs1);
        }
    }
    __syncthreads();
    if (tid < 128) g_partial[(size_t)bj * N + ibase + tid] = sZ[tid];
}

// ---------------- K4: per-row corrections + log-prob of positive ----------------
__global__ void k_rowfix(const float* __restrict__ outm) {
    const int i = blockIdx.x;
    const int d = threadIdx.x;
    const int lane = d & 31, w = d >> 5;
    __shared__ float fi[D];
    __shared__ float red[4];
    fi[d] = g_f[(size_t)i * D + d];
    __syncthreads();

    auto dotw = [&](int j) -> float {
        float p = fi[d] * g_f[(size_t)j * D + d];
        #pragma unroll
        for (int o = 16; o; o >>= 1) p += __shfl_xor_sync(0xffffffffu, p, o);
        if (lane == 0) red[w] = p;
        __syncthreads();
        float r = red[0] + red[1] + red[2] + red[3];
        __syncthreads();
        return r;
    };

    float simpos = (dotw(i ^ BHALF) - 1.0f) * INV_T;

    int cnt = g_cnt[i];
    float corr = 0.0f;
    if (cnt <= 64) {
        for (int k = 0; k < cnt; k++) {
            int j = g_sidx[i * 64 + k];
            float m = g_sval[i * 64 + k];
            corr += m * __expf((dotw(j) - 1.0f) * INV_T);
        }
    } else {
        for (int j = 0; j < N; j++) {
            float m = outm[(size_t)i * N + j];
            if (m > 0.0f) corr += m * __expf((dotw(j) - 1.0f) * INV_T);
        }
    }

    if (d == 0) {
        float Zs = 0.0f;
        for (int b = 0; b < 32; b++) Zs += g_partial[(size_t)b * N + i];
        float Z = Zs - corr;
        g_lp[i] = simpos - logf(Z);
    }
}

// ---------------- K5: loss reduction ----------------
__global__ void k_loss(float* __restrict__ out, int moff) {
    __shared__ float sm[512];
    int t = threadIdx.x;
    float s = 0.0f;
    #pragma unroll
    for (int k = 0; k < 8; k++) s += g_lp[t + k * 512];
    sm[t] = s;
    __syncthreads();
    for (int o = 256; o; o >>= 1) {
        if (t < o) sm[t] += sm[t + o];
        __syncthreads();
    }
    if (t == 0) {
        float loss = -(sm[0] / 4096.0f);
        for (int q = 0; q < moff; q++) out[q] = loss;
    }
}

// ---------------- launch ----------------
extern "C" void kernel_launch(void* const* d_in, const int* in_sizes, int n_in,
                              void* d_out, int out_size) {
    int fidx = (in_sizes[0] == N * D) ? 0 : 1;
    const float* feat = (const float*)d_in[fidx];
    const float* attn = (const float*)d_in[1 - fidx];
    float* out = (float*)d_out;

    long long nn = (long long)N * (long long)N;
    int moff = (int)((long long)out_size - nn);
    if (moff < 0) moff = 0;
    float* outm = out + moff;

    k_norm<<<N, D>>>(feat);
    k_sparsemax<<<N, 512>>>(attn, outm);
    k_gemm<<<dim3(32, 32), 256>>>();
    k_rowfix<<<N, D>>>(outm);
    k_loss<<<1, 512>>>(out, moff);
}

// round 4
// speedup vs baseline: 14.2363x; 1.2585x over previous
#include <cuda_runtime.h>
#include <cstdint>

#define N 4096
#define D 128
#define BHALF 2048
#define INV_T 14.285714285714285714f  /* 1/0.07 */

// ---------------- scratch (static device globals; no allocation) ----------------
__device__ __align__(16) float    g_f[N * D];      // L2-normalized features, fp32
__device__ __align__(16) unsigned g_ftf[N * D];    // tf32-rounded copies (bit pattern)
__device__ int    g_cnt[N];
__device__ int    g_sidx[N * 64];
__device__ float  g_sval[N * 64];
__device__ float  g_partial[32 * N];               // per (j-tile, row) partial Z
__device__ float  g_lp[N];

// ---------------- K1: L2 normalize + tf32 copy ----------------
__global__ void k_norm(const float* __restrict__ feat) {
    int i = blockIdx.x, d = threadIdx.x;
    float v = feat[(size_t)i * D + d];
    float s = v * v;
    #pragma unroll
    for (int o = 16; o; o >>= 1) s += __shfl_xor_sync(0xffffffffu, s, o);
    __shared__ float ws[4];
    if ((d & 31) == 0) ws[d >> 5] = s;
    __syncthreads();
    float tot = ws[0] + ws[1] + ws[2] + ws[3];
    float f = v / sqrtf(tot);
    g_f[(size_t)i * D + d] = f;
    unsigned t;
    asm("cvt.rna.tf32.f32 %0, %1;" : "=r"(t) : "f"(f));
    g_ftf[(size_t)i * D + d] = t;
}

// ---------------- K2: row-wise sparsemax via candidate pruning ----------------
#define CAND_MAX 128

__global__ void __launch_bounds__(512) k_sparsemax(const float* __restrict__ attn,
                                                   float* __restrict__ outm) {
    const int i = blockIdx.x;
    const int tid = threadIdx.x;
    __shared__ float z[N];
    __shared__ float wred[16];
    __shared__ int   wcnt[16];
    __shared__ float s_max, s_tau;
    __shared__ int   s_ccnt, s_fb;
    __shared__ int   s_cidx[CAND_MAX];
    __shared__ float s_cval[CAND_MAX];

    const int j1 = i & (BHALF - 1);
    const int j2 = j1 + BHALF;
    const float4* row4 = (const float4*)(attn + (size_t)i * N);

    float mx = -3.402823466e38f;
    #pragma unroll
    for (int it = 0; it < 2; it++) {
        int v = tid + it * 512;
        float4 r = row4[v];
        int j = v * 4;
        float z0 = (j     == j1 || j     == j2) ? 0.f : r.x * INV_T;
        float z1 = (j + 1 == j1 || j + 1 == j2) ? 0.f : r.y * INV_T;
        float z2 = (j + 2 == j1 || j + 2 == j2) ? 0.f : r.z * INV_T;
        float z3 = (j + 3 == j1 || j + 3 == j2) ? 0.f : r.w * INV_T;
        z[j] = z0; z[j + 1] = z1; z[j + 2] = z2; z[j + 3] = z3;
        mx = fmaxf(mx, fmaxf(fmaxf(z0, z1), fmaxf(z2, z3)));
    }
    #pragma unroll
    for (int o = 16; o; o >>= 1) mx = fmaxf(mx, __shfl_xor_sync(0xffffffffu, mx, o));
    if ((tid & 31) == 0) wred[tid >> 5] = mx;
    if (tid == 0) s_ccnt = 0;
    __syncthreads();
    if (tid == 0) {
        float m = wred[0];
        for (int w = 1; w < 16; w++) m = fmaxf(m, wred[w]);
        s_max = m;
    }
    __syncthreads();

    const float thr = s_max - 1.0f;
    #pragma unroll
    for (int it = 0; it < 2; it++) {
        int j = (tid + it * 512) * 4;
        #pragma unroll
        for (int q = 0; q < 4; q++) {
            float v = z[j + q];
            if (v >= thr) {
                int p = atomicAdd(&s_ccnt, 1);
                if (p < CAND_MAX) { s_cidx[p] = j + q; s_cval[p] = v; }
            }
        }
    }
    __syncthreads();

    if (tid == 0) {
        int cnt = s_ccnt;
        s_fb = (cnt > CAND_MAX);
        if (!s_fb) {
            for (int a = 1; a < cnt; a++) {
                float v = s_cval[a]; int ix = s_cidx[a];
                int b = a - 1;
                while (b >= 0 && (s_cval[b] < v || (s_cval[b] == v && s_cidx[b] > ix))) {
                    s_cval[b + 1] = s_cval[b]; s_cidx[b + 1] = s_cidx[b]; b--;
                }
                s_cval[b + 1] = v; s_cidx[b + 1] = ix;
            }
            float cum = 0.f, cumkz = 1.f; int kz = 1;
            for (int k = 1; k <= cnt; k++) {
                float v = s_cval[k - 1];
                cum += v;
                if (1.0f + (float)k * v > cum) { kz = k; cumkz = cum; }
            }
            float tau = (cumkz - 1.0f) / (float)kz;
            s_tau = tau;
            g_cnt[i] = kz;
            int lim = kz < 64 ? kz : 64;
            for (int k = 0; k < lim; k++) {
                g_sidx[i * 64 + k] = s_cidx[k];
                g_sval[i * 64 + k] = s_cval[k] - tau;
            }
        }
    }
    __syncthreads();

    if (s_fb) {
        float tau = -3.402823466e38f;
        for (int iter = 0; iter < 64; iter++) {
            float s = 0.f; int c = 0;
            for (int j = tid; j < N; j += 512) {
                float v = z[j];
                if (v > tau) { s += v; c++; }
            }
            #pragma unroll
            for (int o = 16; o; o >>= 1) {
                s += __shfl_xor_sync(0xffffffffu, s, o);
                c += __shfl_xor_sync(0xffffffffu, c, o);
            }
            if ((tid & 31) == 0) { wred[tid >> 5] = s; wcnt[tid >> 5] = c; }
            __syncthreads();
            if (tid == 0) {
                float S = 0.f; int C = 0;
                for (int w = 0; w < 16; w++) { S += wred[w]; C += wcnt[w]; }
                s_tau = (S - 1.0f) / (float)C;
            }
            __syncthreads();
            float tn = s_tau;
            if (tn == tau) break;
            tau = tn;
            __syncthreads();
        }
        if (tid == 0) g_cnt[i] = N;
        __syncthreads();
    }

    const float tau = s_tau;
    float* orow = outm + (size_t)i * N;
    #pragma unroll
    for (int it = 0; it < 8; it++) {
        int j = tid + it * 512;
        orow[j] = fmaxf(z[j] - tau, 0.f);
    }
}

// ---------------- K3: symmetric tf32 Gram + exp + row/col partial sums ----------------
__device__ __forceinline__ void mma_tf32(float c[4], const unsigned a[4], const unsigned b[2]) {
    asm volatile(
        "mma.sync.aligned.m16n8k8.row.col.f32.tf32.tf32.f32 "
        "{%0,%1,%2,%3}, {%4,%5,%6,%7}, {%8,%9}, {%0,%1,%2,%3};\n"
        : "+f"(c[0]), "+f"(c[1]), "+f"(c[2]), "+f"(c[3])
        : "r"(a[0]), "r"(a[1]), "r"(a[2]), "r"(a[3]), "r"(b[0]), "r"(b[1]));
}

#define LDA 36

__global__ void __launch_bounds__(256) k_gemm() {
    // triangular tile decode: 528 blocks -> (bi, bj) with bi <= bj
    int t = blockIdx.x, bi = 0;
    while (t >= 32 - bi) { t -= 32 - bi; bi++; }
    const int bj = bi + t;
    const bool diag = (bi == bj);

    __shared__ __align__(16) unsigned As[128 * LDA];
    __shared__ __align__(16) unsigned Bs[128 * LDA];
    __shared__ float sZr[128];
    __shared__ float sZc[4][128];

    const int tid = threadIdx.x;
    const int lane = tid & 31, wid = tid >> 5;
    const int wm = wid >> 1, wn = wid & 1;    // 4 x 2 warp grid -> warp tile 32x64
    const int g = lane >> 2, t4 = lane & 3;

    if (tid < 128) sZr[tid] = 0.0f;

    float acc[2][8][4];
    #pragma unroll
    for (int mt = 0; mt < 2; mt++)
        #pragma unroll
        for (int nt = 0; nt < 8; nt++)
            #pragma unroll
            for (int k = 0; k < 4; k++) acc[mt][nt][k] = 0.0f;

    const int lr = tid >> 1;
    const int lh = tid & 1;

    for (int kc = 0; kc < 4; kc++) {
        #pragma unroll
        for (int q = 0; q < 4; q++) {
            int cv = lh * 4 + q;
            uint4 va = *(const uint4*)(g_ftf + ((size_t)(bi * 128 + lr) * D + kc * 32 + cv * 4));
            *(uint4*)(As + lr * LDA + cv * 4) = va;
            uint4 vb = *(const uint4*)(g_ftf + ((size_t)(bj * 128 + lr) * D + kc * 32 + cv * 4));
            *(uint4*)(Bs + lr * LDA + cv * 4) = vb;
        }
        __syncthreads();

        #pragma unroll
        for (int ks = 0; ks < 4; ks++) {
            unsigned a[2][4], b[8][2];
            #pragma unroll
            for (int mt = 0; mt < 2; mt++) {
                int r0 = wm * 32 + mt * 16 + g;
                a[mt][0] = As[r0 * LDA + ks * 8 + t4];
                a[mt][1] = As[(r0 + 8) * LDA + ks * 8 + t4];
                a[mt][2] = As[r0 * LDA + ks * 8 + t4 + 4];
                a[mt][3] = As[(r0 + 8) * LDA + ks * 8 + t4 + 4];
            }
            #pragma unroll
            for (int nt = 0; nt < 8; nt++) {
                int c0 = wn * 64 + nt * 8 + g;
                b[nt][0] = Bs[c0 * LDA + ks * 8 + t4];
                b[nt][1] = Bs[c0 * LDA + ks * 8 + t4 + 4];
            }
            #pragma unroll
            for (int mt = 0; mt < 2; mt++)
                #pragma unroll
                for (int nt = 0; nt < 8; nt++) mma_tf32(acc[mt][nt], a[mt], b[nt]);
        }
        __syncthreads();
    }

    // epilogue: exp((dot-1)/T); row sums always; col sums for off-diag tiles
    const int ibase = bi * 128, jbase = bj * 128;
    float cp0[8], cp1[8];
    #pragma unroll
    for (int nt = 0; nt < 8; nt++) { cp0[nt] = 0.f; cp1[nt] = 0.f; }

    #pragma unroll
    for (int mt = 0; mt < 2; mt++) {
        int r0 = wm * 32 + mt * 16 + g;
        int gi0 = ibase + r0, gi1 = gi0 + 8;
        float rs0 = 0.f, rs1 = 0.f;
        #pragma unroll
        for (int nt = 0; nt < 8; nt++) {
            int c0 = wn * 64 + nt * 8 + t4 * 2;
            int gj0 = jbase + c0, gj1 = gj0 + 1;
            float e0 = __expf((acc[mt][nt][0] - 1.0f) * INV_T);
            float e1 = __expf((acc[mt][nt][1] - 1.0f) * INV_T);
            float e2 = __expf((acc[mt][nt][2] - 1.0f) * INV_T);
            float e3 = __expf((acc[mt][nt][3] - 1.0f) * INV_T);
            if (diag) {
                if (gj0 == gi0) e0 = 0.f;
                if (gj1 == gi0) e1 = 0.f;
                if (gj0 == gi1) e2 = 0.f;
                if (gj1 == gi1) e3 = 0.f;
            }
            rs0 += e0 + e1; rs1 += e2 + e3;
            cp0[nt] += e0 + e2; cp1[nt] += e1 + e3;
        }
        rs0 += __shfl_xor_sync(0xffffffffu, rs0, 1);
        rs0 += __shfl_xor_sync(0xffffffffu, rs0, 2);
        rs1 += __shfl_xor_sync(0xffffffffu, rs1, 1);
        rs1 += __shfl_xor_sync(0xffffffffu, rs1, 2);
        if (t4 == 0) {   // exactly 2 contributors per row (wn=0,1): commutative -> deterministic
            atomicAdd(&sZr[r0], rs0);
            atomicAdd(&sZr[r0 + 8], rs1);
        }
    }

    if (!diag) {
        // reduce column partials across g-lanes (within warp), deterministic shuffle tree
        #pragma unroll
        for (int nt = 0; nt < 8; nt++) {
            #pragma unroll
            for (int o = 4; o <= 16; o <<= 1) {
                cp0[nt] += __shfl_xor_sync(0xffffffffu, cp0[nt], o);
                cp1[nt] += __shfl_xor_sync(0xffffffffu, cp1[nt], o);
            }
        }
        if (g == 0) {   // lanes 0..3 hold warp col sums
            #pragma unroll
            for (int nt = 0; nt < 8; nt++) {
                int c = wn * 64 + nt * 8 + t4 * 2;
                sZc[wm][c] = cp0[nt];
                sZc[wm][c + 1] = cp1[nt];
            }
        }
    }
    __syncthreads();

    if (tid < 128) {
        g_partial[(size_t)bj * N + ibase + tid] = sZr[tid];   // rows of bi-chunk, slot bj
        if (!diag) {
            float cs = ((sZc[0][tid] + sZc[1][tid]) + sZc[2][tid]) + sZc[3][tid];
            g_partial[(size_t)bi * N + jbase + tid] = cs;      // rows of bj-chunk, slot bi
        }
    }
}

// ---------------- K4: per-row corrections + log-prob (warp per row) ----------------
__global__ void __launch_bounds__(256) k_rowfix(const float* __restrict__ outm) {
    const int wid = threadIdx.x >> 5, lane = threadIdx.x & 31;
    const int i = blockIdx.x * 8 + wid;

    const float4 a = *(const float4*)(g_f + (size_t)i * D + lane * 4);

    auto dot = [&](int j) -> float {
        float4 b = *(const float4*)(g_f + (size_t)j * D + lane * 4);
        float p = a.x * b.x + a.y * b.y + a.z * b.z + a.w * b.w;
        #pragma unroll
        for (int o = 16; o; o >>= 1) p += __shfl_xor_sync(0xffffffffu, p, o);
        return p;
    };

    float simpos = (dot(i ^ BHALF) - 1.0f) * INV_T;

    int cnt = g_cnt[i];
    float corr = 0.0f;
    if (cnt <= 64) {
        for (int k = 0; k < cnt; k++) {
            int j = g_sidx[i * 64 + k];
            float m = g_sval[i * 64 + k];
            corr += m * __expf((dot(j) - 1.0f) * INV_T);
        }
    } else {
        for (int j = 0; j < N; j++) {
            float m = outm[(size_t)i * N + j];
            if (m > 0.0f) corr += m * __expf((dot(j) - 1.0f) * INV_T);
        }
    }

    float zp = g_partial[(size_t)lane * N + i];
    #pragma unroll
    for (int o = 16; o; o >>= 1) zp += __shfl_xor_sync(0xffffffffu, zp, o);

    if (lane == 0) g_lp[i] = simpos - logf(zp - corr);
}

// ---------------- K5: loss reduction ----------------
__global__ void k_loss(float* __restrict__ out, int moff) {
    __shared__ float sm[512];
    int t = threadIdx.x;
    float s = 0.0f;
    #pragma unroll
    for (int k = 0; k < 8; k++) s += g_lp[t + k * 512];
    sm[t] = s;
    __syncthreads();
    for (int o = 256; o; o >>= 1) {
        if (t < o) sm[t] += sm[t + o];
        __syncthreads();
    }
    if (t == 0) {
        float loss = -(sm[0] / 4096.0f);
        for (int q = 0; q < moff; q++) out[q] = loss;
    }
}

// ---------------- launch ----------------
extern "C" void kernel_launch(void* const* d_in, const int* in_sizes, int n_in,
                              void* d_out, int out_size) {
    int fidx = (in_sizes[0] == N * D) ? 0 : 1;
    const float* feat = (const float*)d_in[fidx];
    const float* attn = (const float*)d_in[1 - fidx];
    float* out = (float*)d_out;

    long long nn = (long long)N * (long long)N;
    int moff = (int)((long long)out_size - nn);
    if (moff < 0) moff = 0;
    float* outm = out + moff;

    k_norm<<<N, D>>>(feat);
    k_sparsemax<<<N, 512>>>(attn, outm);
    k_gemm<<<528, 256>>>();
    k_rowfix<<<512, 256>>>(outm);
    k_loss<<<1, 512>>>(out, moff);
}

// round 5
// speedup vs baseline: 14.3624x; 1.0089x over previous
#include <cuda_runtime.h>
#include <cstdint>

#define N 4096
#define D 128
#define BHALF 2048
#define INV_T 14.285714285714285714f  /* 1/0.07 */

// ---------------- scratch (static device globals; no allocation) ----------------
__device__ __align__(16) float    g_f[N * D];      // L2-normalized features, fp32
__device__ __align__(16) unsigned g_ftf[N * D];    // tf32-rounded copies (bit pattern)
__device__ int    g_cnt[N];
__device__ int    g_sidx[N * 64];
__device__ float  g_sval[N * 64];
__device__ float  g_partial[32 * N];               // per (j-tile, row) partial Z
__device__ float  g_lp[N];

// ---------------- K2: fused L2-norm + row-wise sparsemax (register resident) ----------------
#define CAND_MAX 128

__global__ void __launch_bounds__(512) k_sparsemax(const float* __restrict__ feat,
                                                   const float* __restrict__ attn,
                                                   float* __restrict__ outm) {
    const int i = blockIdx.x;
    const int tid = threadIdx.x;
    __shared__ float wred[16];
    __shared__ int   wcnt[16];
    __shared__ float s_max, s_tau;
    __shared__ int   s_ccnt, s_fb;
    __shared__ int   s_cidx[CAND_MAX];
    __shared__ float s_cval[CAND_MAX];

    // fused norm prologue: warp 0 normalizes feature row i (no cross-warp sync needed)
    if (tid < 32) {
        float4 v = *(const float4*)(feat + (size_t)i * D + tid * 4);
        float s = v.x * v.x + v.y * v.y + v.z * v.z + v.w * v.w;
        #pragma unroll
        for (int o = 16; o; o >>= 1) s += __shfl_xor_sync(0xffffffffu, s, o);
        float r = sqrtf(s);
        float4 f = make_float4(v.x / r, v.y / r, v.z / r, v.w / r);
        *(float4*)(g_f + (size_t)i * D + tid * 4) = f;
        uint4 tf;
        asm("cvt.rna.tf32.f32 %0, %1;" : "=r"(tf.x) : "f"(f.x));
        asm("cvt.rna.tf32.f32 %0, %1;" : "=r"(tf.y) : "f"(f.y));
        asm("cvt.rna.tf32.f32 %0, %1;" : "=r"(tf.z) : "f"(f.z));
        asm("cvt.rna.tf32.f32 %0, %1;" : "=r"(tf.w) : "f"(f.w));
        *(uint4*)(g_ftf + (size_t)i * D + tid * 4) = tf;
    }

    const int j1 = i & (BHALF - 1);
    const int j2 = j1 + BHALF;
    const float* row = attn + (size_t)i * N;

    // pass A: load row into registers (coalesced, MLP=8), mask positives/diag, track max
    float z[8];
    float mx = -3.402823466e38f;
    #pragma unroll
    for (int it = 0; it < 8; it++) {
        int j = tid + it * 512;
        float v = row[j] * INV_T;
        if (j == j1 || j == j2) v = 0.f;
        z[it] = v;
        mx = fmaxf(mx, v);
    }
    #pragma unroll
    for (int o = 16; o; o >>= 1) mx = fmaxf(mx, __shfl_xor_sync(0xffffffffu, mx, o));
    if ((tid & 31) == 0) wred[tid >> 5] = mx;
    if (tid == 0) s_ccnt = 0;
    __syncthreads();
    if (tid == 0) {
        float m = wred[0];
        for (int w = 1; w < 16; w++) m = fmaxf(m, wred[w]);
        s_max = m;
    }
    __syncthreads();

    // pass B: gather candidates z >= max - 1 (sparsemax support bound)
    const float thr = s_max - 1.0f;
    #pragma unroll
    for (int it = 0; it < 8; it++) {
        if (z[it] >= thr) {
            int p = atomicAdd(&s_ccnt, 1);
            if (p < CAND_MAX) { s_cidx[p] = tid + it * 512; s_cval[p] = z[it]; }
        }
    }
    __syncthreads();

    if (tid == 0) {
        int cnt = s_ccnt;
        s_fb = (cnt > CAND_MAX);
        if (!s_fb) {
            // insertion sort desc by (value, index asc) -> deterministic
            for (int a = 1; a < cnt; a++) {
                float v = s_cval[a]; int ix = s_cidx[a];
                int b = a - 1;
                while (b >= 0 && (s_cval[b] < v || (s_cval[b] == v && s_cidx[b] > ix))) {
                    s_cval[b + 1] = s_cval[b]; s_cidx[b + 1] = s_cidx[b]; b--;
                }
                s_cval[b + 1] = v; s_cidx[b + 1] = ix;
            }
            // reference formula: fp32 sequential cumsum over descending values
            float cum = 0.f, cumkz = 1.f; int kz = 1;
            for (int k = 1; k <= cnt; k++) {
                float v = s_cval[k - 1];
                cum += v;
                if (1.0f + (float)k * v > cum) { kz = k; cumkz = cum; }
            }
            float tau = (cumkz - 1.0f) / (float)kz;
            s_tau = tau;
            g_cnt[i] = kz;
            int lim = kz < 64 ? kz : 64;
            for (int k = 0; k < lim; k++) {
                g_sidx[i * 64 + k] = s_cidx[k];
                g_sval[i * 64 + k] = s_cval[k] - tau;
            }
        }
    }
    __syncthreads();

    if (s_fb) {
        // fp32 Michelot fallback (safety only)
        float tau = -3.402823466e38f;
        for (int iter = 0; iter < 64; iter++) {
            float s = 0.f; int c = 0;
            #pragma unroll
            for (int it = 0; it < 8; it++) {
                float v = z[it];
                if (v > tau) { s += v; c++; }
            }
            #pragma unroll
            for (int o = 16; o; o >>= 1) {
                s += __shfl_xor_sync(0xffffffffu, s, o);
                c += __shfl_xor_sync(0xffffffffu, c, o);
            }
            if ((tid & 31) == 0) { wred[tid >> 5] = s; wcnt[tid >> 5] = c; }
            __syncthreads();
            if (tid == 0) {
                float S = 0.f; int C = 0;
                for (int w = 0; w < 16; w++) { S += wred[w]; C += wcnt[w]; }
                s_tau = (S - 1.0f) / (float)C;
            }
            __syncthreads();
            float tn = s_tau;
            if (tn == tau) break;
            tau = tn;
            __syncthreads();
        }
        if (tid == 0) g_cnt[i] = N;
        __syncthreads();
    }

    // pass C: write masked row from registers (coalesced scalar stores; outm is 4B-aligned)
    const float tau = s_tau;
    float* orow = outm + (size_t)i * N;
    #pragma unroll
    for (int it = 0; it < 8; it++) {
        orow[tid + it * 512] = fmaxf(z[it] - tau, 0.f);
    }
}

// ---------------- K3: symmetric tf32 Gram + exp + row/col partial sums ----------------
__device__ __forceinline__ void mma_tf32(float c[4], const unsigned a[4], const unsigned b[2]) {
    asm volatile(
        "mma.sync.aligned.m16n8k8.row.col.f32.tf32.tf32.f32 "
        "{%0,%1,%2,%3}, {%4,%5,%6,%7}, {%8,%9}, {%0,%1,%2,%3};\n"
        : "+f"(c[0]), "+f"(c[1]), "+f"(c[2]), "+f"(c[3])
        : "r"(a[0]), "r"(a[1]), "r"(a[2]), "r"(a[3]), "r"(b[0]), "r"(b[1]));
}

#define LDA 36

__global__ void __launch_bounds__(256) k_gemm() {
    // triangular tile decode: 528 blocks -> (bi, bj) with bi <= bj
    int t = blockIdx.x, bi = 0;
    while (t >= 32 - bi) { t -= 32 - bi; bi++; }
    const int bj = bi + t;
    const bool diag = (bi == bj);

    __shared__ __align__(16) unsigned As[128 * LDA];
    __shared__ __align__(16) unsigned Bs[128 * LDA];
    __shared__ float sZr[128];
    __shared__ float sZc[4][128];

    const int tid = threadIdx.x;
    const int lane = tid & 31, wid = tid >> 5;
    const int wm = wid >> 1, wn = wid & 1;
    const int g = lane >> 2, t4 = lane & 3;

    if (tid < 128) sZr[tid] = 0.0f;

    float acc[2][8][4];
    #pragma unroll
    for (int mt = 0; mt < 2; mt++)
        #pragma unroll
        for (int nt = 0; nt < 8; nt++)
            #pragma unroll
            for (int k = 0; k < 4; k++) acc[mt][nt][k] = 0.0f;

    const int lr = tid >> 1;
    const int lh = tid & 1;
    const unsigned* Bp = diag ? As : Bs;

    for (int kc = 0; kc < 4; kc++) {
        #pragma unroll
        for (int q = 0; q < 4; q++) {
            int cv = lh * 4 + q;
            uint4 va = *(const uint4*)(g_ftf + ((size_t)(bi * 128 + lr) * D + kc * 32 + cv * 4));
            *(uint4*)(As + lr * LDA + cv * 4) = va;
            if (!diag) {
                uint4 vb = *(const uint4*)(g_ftf + ((size_t)(bj * 128 + lr) * D + kc * 32 + cv * 4));
                *(uint4*)(Bs + lr * LDA + cv * 4) = vb;
            }
        }
        __syncthreads();

        #pragma unroll
        for (int ks = 0; ks < 4; ks++) {
            unsigned a[2][4], b[8][2];
            #pragma unroll
            for (int mt = 0; mt < 2; mt++) {
                int r0 = wm * 32 + mt * 16 + g;
                a[mt][0] = As[r0 * LDA + ks * 8 + t4];
                a[mt][1] = As[(r0 + 8) * LDA + ks * 8 + t4];
                a[mt][2] = As[r0 * LDA + ks * 8 + t4 + 4];
                a[mt][3] = As[(r0 + 8) * LDA + ks * 8 + t4 + 4];
            }
            #pragma unroll
            for (int nt = 0; nt < 8; nt++) {
                int c0 = wn * 64 + nt * 8 + g;
                b[nt][0] = Bp[c0 * LDA + ks * 8 + t4];
                b[nt][1] = Bp[c0 * LDA + ks * 8 + t4 + 4];
            }
            #pragma unroll
            for (int mt = 0; mt < 2; mt++)
                #pragma unroll
                for (int nt = 0; nt < 8; nt++) mma_tf32(acc[mt][nt], a[mt], b[nt]);
        }
        __syncthreads();
    }

    // epilogue: exp((dot-1)/T); row sums always; col sums for off-diag tiles
    const int ibase = bi * 128, jbase = bj * 128;
    float cp0[8], cp1[8];
    #pragma unroll
    for (int nt = 0; nt < 8; nt++) { cp0[nt] = 0.f; cp1[nt] = 0.f; }

    #pragma unroll
    for (int mt = 0; mt < 2; mt++) {
        int r0 = wm * 32 + mt * 16 + g;
        int gi0 = ibase + r0, gi1 = gi0 + 8;
        float rs0 = 0.f, rs1 = 0.f;
        #pragma unroll
        for (int nt = 0; nt < 8; nt++) {
            int c0 = wn * 64 + nt * 8 + t4 * 2;
            int gj0 = jbase + c0, gj1 = gj0 + 1;
            float e0 = __expf((acc[mt][nt][0] - 1.0f) * INV_T);
            float e1 = __expf((acc[mt][nt][1] - 1.0f) * INV_T);
            float e2 = __expf((acc[mt][nt][2] - 1.0f) * INV_T);
            float e3 = __expf((acc[mt][nt][3] - 1.0f) * INV_T);
            if (diag) {
                if (gj0 == gi0) e0 = 0.f;
                if (gj1 == gi0) e1 = 0.f;
                if (gj0 == gi1) e2 = 0.f;
                if (gj1 == gi1) e3 = 0.f;
            }
            rs0 += e0 + e1; rs1 += e2 + e3;
            cp0[nt] += e0 + e2; cp1[nt] += e1 + e3;
        }
        rs0 += __shfl_xor_sync(0xffffffffu, rs0, 1);
        rs0 += __shfl_xor_sync(0xffffffffu, rs0, 2);
        rs1 += __shfl_xor_sync(0xffffffffu, rs1, 1);
        rs1 += __shfl_xor_sync(0xffffffffu, rs1, 2);
        if (t4 == 0) {
            atomicAdd(&sZr[r0], rs0);
            atomicAdd(&sZr[r0 + 8], rs1);
        }
    }

    if (!diag) {
        #pragma unroll
        for (int nt = 0; nt < 8; nt++) {
            #pragma unroll
            for (int o = 4; o <= 16; o <<= 1) {
                cp0[nt] += __shfl_xor_sync(0xffffffffu, cp0[nt], o);
                cp1[nt] += __shfl_xor_sync(0xffffffffu, cp1[nt], o);
            }
        }
        if (g == 0) {
            #pragma unroll
            for (int nt = 0; nt < 8; nt++) {
                int c = wn * 64 + nt * 8 + t4 * 2;
                sZc[wm][c] = cp0[nt];
                sZc[wm][c + 1] = cp1[nt];
            }
        }
    }
    __syncthreads();

    if (tid < 128) {
        g_partial[(size_t)bj * N + ibase + tid] = sZr[tid];
        if (!diag) {
            float cs = ((sZc[0][tid] + sZc[1][tid]) + sZc[2][tid]) + sZc[3][tid];
            g_partial[(size_t)bi * N + jbase + tid] = cs;
        }
    }
}

// ---------------- K4: per-row corrections + log-prob (warp per row) ----------------
__global__ void __launch_bounds__(256) k_rowfix(const float* __restrict__ outm) {
    const int wid = threadIdx.x >> 5, lane = threadIdx.x & 31;
    const int i = blockIdx.x * 8 + wid;

    const float4 a = *(const float4*)(g_f + (size_t)i * D + lane * 4);

    auto dot = [&](int j) -> float {
        float4 b = *(const float4*)(g_f + (size_t)j * D + lane * 4);
        float p = a.x * b.x + a.y * b.y + a.z * b.z + a.w * b.w;
        #pragma unroll
        for (int o = 16; o; o >>= 1) p += __shfl_xor_sync(0xffffffffu, p, o);
        return p;
    };

    float simpos = (dot(i ^ BHALF) - 1.0f) * INV_T;

    int cnt = g_cnt[i];
    float corr = 0.0f;
    if (cnt <= 64) {
        for (int k = 0; k < cnt; k++) {
            int j = g_sidx[i * 64 + k];
            float m = g_sval[i * 64 + k];
            corr += m * __expf((dot(j) - 1.0f) * INV_T);
        }
    } else {
        for (int j = 0; j < N; j++) {
            float m = outm[(size_t)i * N + j];
            if (m > 0.0f) corr += m * __expf((dot(j) - 1.0f) * INV_T);
        }
    }

    float zp = g_partial[(size_t)lane * N + i];
    #pragma unroll
    for (int o = 16; o; o >>= 1) zp += __shfl_xor_sync(0xffffffffu, zp, o);

    if (lane == 0) g_lp[i] = simpos - logf(zp - corr);
}

// ---------------- K5: loss reduction ----------------
__global__ void k_loss(float* __restrict__ out, int moff) {
    __shared__ float sm[512];
    int t = threadIdx.x;
    float s = 0.0f;
    #pragma unroll
    for (int k = 0; k < 8; k++) s += g_lp[t + k * 512];
    sm[t] = s;
    __syncthreads();
    for (int o = 256; o; o >>= 1) {
        if (t < o) sm[t] += sm[t + o];
        __syncthreads();
    }
    if (t == 0) {
        float loss = -(sm[0] / 4096.0f);
        for (int q = 0; q < moff; q++) out[q] = loss;
    }
}

// ---------------- launch ----------------
extern "C" void kernel_launch(void* const* d_in, const int* in_sizes, int n_in,
                              void* d_out, int out_size) {
    int fidx = (in_sizes[0] == N * D) ? 0 : 1;
    const float* feat = (const float*)d_in[fidx];
    const float* attn = (const float*)d_in[1 - fidx];
    float* out = (float*)d_out;

    long long nn = (long long)N * (long long)N;
    int moff = (int)((long long)out_size - nn);
    if (moff < 0) moff = 0;
    float* outm = out + moff;

    k_sparsemax<<<N, 512>>>(feat, attn, outm);
    k_gemm<<<528, 256>>>();
    k_rowfix<<<512, 256>>>(outm);
    k_loss<<<1, 512>>>(out, moff);
}